// round 17
// baseline (speedup 1.0000x reference)
#include <cuda_runtime.h>
#include <cuda_fp16.h>
#include <math.h>
#include <stdint.h>

// Problem constants
#define NN 49152
#define CC 512
#define HH 8
#define KK 48
#define DD 64
#define PP 1024            // NN / KK
#define C3 1536            // 3*C
#define C2 1024            // 2*C

// ---------------------------------------------------------------------------
// Scratch (device globals; no runtime allocation). Intermediates are fp16.
// ---------------------------------------------------------------------------
__device__ __half g_xln_s[(size_t)NN * CC];   // LN-transformed inputs, fp16
__device__ __half g_xln_b[(size_t)NN * CC];
__device__ __half g_qkv_s[(size_t)NN * C3];
__device__ __half g_qkv_b[(size_t)NN * C3];
__device__ __half g_h1[(size_t)NN * C2];
__device__ __half g_qf[(size_t)NN * CC];
__device__ __half g_attn_s[(size_t)NN * CC];
__device__ __half g_attn_b[(size_t)NN * CC];
// Packed fp16 weights, fragment-major, grouped by 64-k chunk:
// u32 index = ((chunk*(N/128) + nblk)*4 + k16step)*1024 + nfrag*64 + lane*2 + reg
__device__ uint32_t g_wp_qs[(size_t)(CC / 2) * C3];
__device__ uint32_t g_wp_qb[(size_t)(CC / 2) * C3];
__device__ uint32_t g_wp_f1[(size_t)(C2 / 2) * C2];
__device__ uint32_t g_wp_f2[(size_t)(C2 / 2) * CC];
__device__ uint32_t g_wp_os[(size_t)(CC / 2) * CC];
__device__ uint32_t g_wp_ob[(size_t)(CC / 2) * CC];

// ---------------------------------------------------------------------------
// Helpers (base-target PTX, sm_80+ only)
// ---------------------------------------------------------------------------
__device__ __forceinline__ uint32_t pack2h(float a, float b) {
    __half2 h = __floats2half2_rn(a, b);
    return *reinterpret_cast<uint32_t*>(&h);
}

__device__ __forceinline__ uint32_t smem_u32(const void* p) {
    uint32_t a;
    asm("{ .reg .u64 t; cvta.to.shared.u64 t, %1; cvt.u32.u64 %0, t; }"
        : "=r"(a) : "l"(p));
    return a;
}

__device__ __forceinline__ void mma_f16(float* d, const uint32_t* a, const uint32_t* b) {
    asm volatile(
        "mma.sync.aligned.m16n8k16.row.col.f32.f16.f16.f32 "
        "{%0,%1,%2,%3}, {%4,%5,%6,%7}, {%8,%9}, {%0,%1,%2,%3};"
        : "+f"(d[0]), "+f"(d[1]), "+f"(d[2]), "+f"(d[3])
        : "r"(a[0]), "r"(a[1]), "r"(a[2]), "r"(a[3]), "r"(b[0]), "r"(b[1]));
}

__device__ __forceinline__ void cp16(uint32_t saddr, const void* gptr) {
    asm volatile("cp.async.cg.shared.global [%0], [%1], 16;" :: "r"(saddr), "l"(gptr));
}
#define CP_COMMIT() asm volatile("cp.async.commit_group;" ::: "memory")
#define CP_WAIT0()  asm volatile("cp.async.wait_group 0;" ::: "memory")
#define CP_WAIT1()  asm volatile("cp.async.wait_group 1;" ::: "memory")

// ---------------------------------------------------------------------------
// Weight pack body: w [K,N] fp32 -> fp16 pairs, fragment-major, 64-k chunks
// ---------------------------------------------------------------------------
__device__ __forceinline__ void prep_body(const float* __restrict__ w,
                                          uint32_t* __restrict__ out,
                                          int Kd, int Nd, int idx)
{
    int n  = idx % Nd;
    int k  = (idx / Nd) << 1;                      // even k
    float v0 = w[(size_t)k * Nd + n];
    float v1 = w[(size_t)(k + 1) * Nd + n];
    int cc   = k >> 6;                             // 64-k chunk
    int step = (k >> 4) & 3;
    int nblk = n >> 7, nn = n & 127;
    int nfrag = nn >> 3;
    int lane  = (nn & 7) * 4 + ((k & 7) >> 1);
    int reg   = (k & 15) >> 3;
    size_t o = ((size_t)(cc * (Nd >> 7) + nblk) * 4 + step) * 1024
             + nfrag * 64 + lane * 2 + reg;
    out[o] = pack2h(v0, v1);
}

// One launch packs all 6 weight matrices (segment if-chain).
__global__ void __launch_bounds__(256)
prep_all(const float* __restrict__ w0, const float* __restrict__ w1,
         const float* __restrict__ w2, const float* __restrict__ w3,
         const float* __restrict__ w4, const float* __restrict__ w5,
         uint32_t* __restrict__ o0, uint32_t* __restrict__ o1,
         uint32_t* __restrict__ o2, uint32_t* __restrict__ o3,
         uint32_t* __restrict__ o4, uint32_t* __restrict__ o5)
{
    int idx = blockIdx.x * 256 + threadIdx.x;
    if (idx < 393216)        prep_body(w0, o0, 512, 1536, idx);
    else if (idx < 786432)   prep_body(w1, o1, 512, 1536, idx - 393216);
    else if (idx < 1310720)  prep_body(w2, o2, 1024, 1024, idx - 786432);
    else if (idx < 1572864)  prep_body(w3, o3, 1024, 512, idx - 1310720);
    else if (idx < 1703936)  prep_body(w4, o4, 512, 512, idx - 1572864);
    else if (idx < 1835008)  prep_body(w5, o5, 512, 512, idx - 1703936);
}

// ---------------------------------------------------------------------------
// Fused LayerNorm (both streams via grid.y): fp32 in -> fp16 out, warp/row
// ---------------------------------------------------------------------------
__global__ void __launch_bounds__(256)
ln_fp16(const float* __restrict__ x0, const float* __restrict__ x1,
        const float* __restrict__ g0, const float* __restrict__ b0,
        const float* __restrict__ g1, const float* __restrict__ b1,
        __half* __restrict__ o0, __half* __restrict__ o1)
{
    const float* x = blockIdx.y ? x1 : x0;
    const float* g = blockIdx.y ? g1 : g0;
    const float* b = blockIdx.y ? b1 : b0;
    __half* o = blockIdx.y ? o1 : o0;

    const int row  = blockIdx.x * 8 + (threadIdx.x >> 5);
    const int lane = threadIdx.x & 31;
    const float* xr = x + (size_t)row * CC;
    float4 v[4];
    float s = 0.f, sq = 0.f;
    #pragma unroll
    for (int j = 0; j < 4; j++) {
        v[j] = *(const float4*)(xr + lane * 4 + 128 * j);
        s  += v[j].x + v[j].y + v[j].z + v[j].w;
        sq += v[j].x * v[j].x + v[j].y * v[j].y + v[j].z * v[j].z + v[j].w * v[j].w;
    }
    #pragma unroll
    for (int off = 16; off > 0; off >>= 1) {
        s  += __shfl_xor_sync(0xffffffffu, s, off);
        sq += __shfl_xor_sync(0xffffffffu, sq, off);
    }
    const float m = s * (1.f / CC);
    const float r = rsqrtf(sq * (1.f / CC) - m * m + 1e-5f);
    __half* orow = o + (size_t)row * CC;
    #pragma unroll
    for (int j = 0; j < 4; j++) {
        const int col = lane * 4 + 128 * j;
        float4 g4 = *(const float4*)(g + col);
        float4 b4 = *(const float4*)(b + col);
        uint2 w;
        w.x = pack2h((v[j].x - m) * r * g4.x + b4.x, (v[j].y - m) * r * g4.y + b4.y);
        w.y = pack2h((v[j].z - m) * r * g4.z + b4.z, (v[j].w - m) * r * g4.w + b4.w);
        *(uint2*)(orow + col) = w;
    }
}

// ---------------------------------------------------------------------------
// Fully-async FP16 mma.sync GEMM, 3-stage cp.async pipeline.
// 256 threads (8 warps, 2x4), warp tile 64x32 -> 4 warps/SMSP for latency
// hiding. 2 CTAs/SM (<=128 regs). Dual-problem via blockIdx.z when grid.z=2.
// AMODE: 0 plain fp16, 2 concat(A|A2)
// EPI:   0 bias->fp16, 1 bias+scatter->fp16, 2 bias+GELU->fp16, 3 bias+residual->fp32
// ---------------------------------------------------------------------------
template<int AMODE, int EPI>
__global__ void __launch_bounds__(256, 2)
gemm_mma(const __half* __restrict__ A0, const __half* __restrict__ A1,
         const __half* __restrict__ A2, int lda,
         const uint32_t* __restrict__ Bp0, const uint32_t* __restrict__ Bp1,
         int nbCols,
         const float* __restrict__ bias0, const float* __restrict__ bias1,
         void* __restrict__ Cov0, void* __restrict__ Cov1, int ldc,
         const int* __restrict__ scat,
         const float* __restrict__ res0, const float* __restrict__ res1,
         int Kd)
{
    extern __shared__ uint32_t sm[];
    // A: 3 stages x 16384 B (swizzled). B: 3 stages x 4096 u32 (frag-major).
    uint32_t* sB = sm + 12288;
    uint32_t sAaddr;
    asm("{ .reg .u64 t; cvta.to.shared.u64 t, %1; cvt.u32.u64 %0, t; }"
        : "=r"(sAaddr) : "l"((const void*)sm));

    const int z = blockIdx.z;
    const __half*    A    = z ? A1 : A0;
    const uint32_t*  Bp   = z ? Bp1 : Bp0;
    const float*     bias = z ? bias1 : bias0;
    void*            Cov  = z ? Cov1 : Cov0;
    const float*     res  = z ? res1 : res0;

    const int tid  = threadIdx.x;
    const int lane = tid & 31, wid = tid >> 5;
    const int brow = blockIdx.y * 128, bcol = blockIdx.x * 128;
    const int nblk = blockIdx.x;
    const int mf0 = (wid >> 2) * 4;          // 2 m-blocks of 64 rows
    const int nf0 = (wid & 3) * 4;           // 4 n-blocks of 32 cols

    float acc[4][4][4];
    #pragma unroll
    for (int a = 0; a < 4; a++)
        #pragma unroll
        for (int b = 0; b < 4; b++)
            #pragma unroll
            for (int r = 0; r < 4; r++) acc[a][b][r] = 0.f;

    // A copy: 128 rows x 8 16B-chunks = 1024 cp16; 256 threads -> 4 each
    const int ar0 = tid >> 3;                // 0..31
    const int ac  = tid & 7;                 // chunk in row
    auto CPA = [&](int c, int st) {
        const int k0 = c << 6;
        const __half* src;
        int kk;
        if (AMODE == 2) {
            src = (k0 < 512) ? A : A2;
            kk  = (k0 < 512) ? k0 : k0 - 512;
        } else { src = A; kk = k0; }
        #pragma unroll
        for (int i = 0; i < 4; i++) {
            const int row = ar0 + 32 * i;
            uint32_t dst = sAaddr + st * 16384 + row * 128 + ((ac ^ (row & 7)) << 4);
            cp16(dst, src + (size_t)(brow + row) * lda + kk + ac * 8);
        }
    };
    auto CPB = [&](int c, int st) {
        const uint32_t* src = Bp + ((size_t)(c * nbCols + nblk) << 12);
        uint32_t sBaddr = sAaddr + 49152;
        #pragma unroll
        for (int j = 0; j < 4; j++)
            cp16(sBaddr + (st * 4096 + (j << 10) + (tid << 2)) * 4,
                 src + (j << 10) + (tid << 2));
    };

    auto COMPUTE = [&](int st) {
        #pragma unroll
        for (int ks = 0; ks < 4; ks++) {
            uint32_t af[4][4], bf[4][2];
            #pragma unroll
            for (int mi = 0; mi < 4; mi++) {
                uint32_t addr = sAaddr + st * 16384
                              + ((mf0 + mi) * 16 + (lane & 15)) * 128
                              + ((((ks << 1) + (lane >> 4)) ^ (lane & 7)) << 4);
                asm volatile(
                    "ldmatrix.sync.aligned.m8n8.x4.shared.b16 {%0,%1,%2,%3}, [%4];"
                    : "=r"(af[mi][0]), "=r"(af[mi][1]), "=r"(af[mi][2]), "=r"(af[mi][3])
                    : "r"(addr));
            }
            #pragma unroll
            for (int ni = 0; ni < 4; ni++) {
                uint2 t = *(const uint2*)(sB + st * 4096 + ks * 1024 +
                                          (nf0 + ni) * 64 + lane * 2);
                bf[ni][0] = t.x; bf[ni][1] = t.y;
            }
            #pragma unroll
            for (int mi = 0; mi < 4; mi++)
                #pragma unroll
                for (int ni = 0; ni < 4; ni++)
                    mma_f16(acc[mi][ni], af[mi], bf[ni]);
        }
    };

    const int KC = Kd >> 6;
    CPA(0, 0); CPB(0, 0); CP_COMMIT();
    CPA(1, 1); CPB(1, 1); CP_COMMIT();
    int st = 0;
    for (int c = 0; c < KC; c++) {
        if (c + 1 < KC) CP_WAIT1(); else CP_WAIT0();
        __syncthreads();
        if (c + 2 < KC) {
            // stage (st+2)%3 == stage of chunk c-1; safe after this barrier
            const int si = (st + 2 >= 3) ? st - 1 : st + 2;
            CPA(c + 2, si); CPB(c + 2, si); CP_COMMIT();
        }
        COMPUTE(st);
        st = (st + 1 == 3) ? 0 : st + 1;
    }

    // ---- epilogue: fused bias / gelu / scatter / residual
    const int wm = (wid >> 2) * 64, wn = (wid & 3) * 32;
    float*  Cf = (float*)Cov;
    __half* Ch = (__half*)Cov;
    #pragma unroll
    for (int mi = 0; mi < 4; mi++) {
        const int ra = brow + wm + mi * 16 + (lane >> 2);
        const int rb = ra + 8;
        const int ora = (EPI == 1) ? scat[ra] : ra;
        const int orb = (EPI == 1) ? scat[rb] : rb;
        #pragma unroll
        for (int ni = 0; ni < 4; ni++) {
            const int col = bcol + wn + ni * 8 + (lane & 3) * 2;
            const float b0 = bias[col], b1 = bias[col + 1];
            float v0 = acc[mi][ni][0] + b0, v1 = acc[mi][ni][1] + b1;
            float v2 = acc[mi][ni][2] + b0, v3 = acc[mi][ni][3] + b1;
            if (EPI == 2) {
                v0 = 0.5f * v0 * (1.f + erff(v0 * 0.7071067811865475f));
                v1 = 0.5f * v1 * (1.f + erff(v1 * 0.7071067811865475f));
                v2 = 0.5f * v2 * (1.f + erff(v2 * 0.7071067811865475f));
                v3 = 0.5f * v3 * (1.f + erff(v3 * 0.7071067811865475f));
            }
            if (EPI == 3) {
                v0 += res[(size_t)ra * ldc + col];
                v1 += res[(size_t)ra * ldc + col + 1];
                v2 += res[(size_t)rb * ldc + col];
                v3 += res[(size_t)rb * ldc + col + 1];
                *(float2*)(Cf + (size_t)ra * ldc + col) = make_float2(v0, v1);
                *(float2*)(Cf + (size_t)rb * ldc + col) = make_float2(v2, v3);
            } else {
                *(uint32_t*)(Ch + (size_t)ora * ldc + col) = pack2h(v0, v1);
                *(uint32_t*)(Ch + (size_t)orb * ldc + col) = pack2h(v2, v3);
            }
        }
    }
}

// ---------------------------------------------------------------------------
// Tensor-core per-(patch, head, stream) attention (R12, unchanged).
// ---------------------------------------------------------------------------
#define AST 72    // q/k/v smem stride in halves (144 B rows, conflict-free)
#define SCST 52   // score fp32 stride
#define PST 56    // prob fp16 stride (112 B rows)
__global__ void __launch_bounds__(128)
patch_attn_kernel(const __half* __restrict__ qf,
                  const __half* __restrict__ qkv_s,
                  const __half* __restrict__ qkv_b,
                  const int* __restrict__ order,
                  __half* __restrict__ attn_s,
                  __half* __restrict__ attn_b)
{
    const int p = blockIdx.x >> 3;
    const int h = blockIdx.x & 7;
    const __half* qkv = blockIdx.y ? qkv_b : qkv_s;
    __half* out = blockIdx.y ? attn_b : attn_s;

    __shared__ __half Qh[48 * AST];
    __shared__ __half Kh[48 * AST];
    __shared__ __half Vh[48 * AST];
    __shared__ float  scs[48 * SCST];
    __shared__ __half Ph[48 * PST];

    const int tid = threadIdx.x, lane = tid & 31, wid = tid >> 5;
    const size_t rowbase = (size_t)p * KK;
    const uint32_t qa = smem_u32(Qh), ka = smem_u32(Kh), va = smem_u32(Vh);
    const uint32_t pa = smem_u32(Ph);

    #pragma unroll
    for (int i = 0; i < 9; i++) {
        const int idx = i * 128 + tid;
        const int row = idx >> 3, c = idx & 7;
        const int seg = row / 48;            // 0=q, 1=k, 2=v
        const int r = row - seg * 48;
        const __half* src = (seg == 0)
            ? qf + (rowbase + r) * CC + h * DD
            : qkv + (rowbase + r) * C3 + (seg == 1 ? 512 : 1024) + h * DD;
        const uint32_t base = (seg == 0) ? qa : (seg == 1) ? ka : va;
        cp16(base + r * (AST * 2) + c * 16, src + c * 8);
    }
    CP_COMMIT();
    CP_WAIT0();
    __syncthreads();

    for (int t = wid; t < 18; t += 4) {
        const int mf = t / 6, nf = t % 6;
        float d4[4] = { 0.f, 0.f, 0.f, 0.f };
        #pragma unroll
        for (int ks = 0; ks < 4; ks++) {
            uint32_t a[4], b[2];
            uint32_t aaddr = qa + ((mf * 16 + (lane & 15)) * AST
                                   + ks * 16 + ((lane >> 4) << 3)) * 2;
            asm volatile("ldmatrix.sync.aligned.m8n8.x4.shared.b16 {%0,%1,%2,%3}, [%4];"
                         : "=r"(a[0]), "=r"(a[1]), "=r"(a[2]), "=r"(a[3]) : "r"(aaddr));
            uint32_t baddr = ka + ((nf * 8 + (lane & 7)) * AST
                                   + ks * 16 + (((lane >> 3) & 1) << 3)) * 2;
            asm volatile("ldmatrix.sync.aligned.m8n8.x2.shared.b16 {%0,%1}, [%2];"
                         : "=r"(b[0]), "=r"(b[1]) : "r"(baddr));
            mma_f16(d4, a, b);
        }
        const int r0 = mf * 16 + (lane >> 2), c0 = nf * 8 + (lane & 3) * 2;
        scs[r0 * SCST + c0]       = d4[0] * 0.125f;
        scs[r0 * SCST + c0 + 1]   = d4[1] * 0.125f;
        scs[(r0 + 8) * SCST + c0]     = d4[2] * 0.125f;
        scs[(r0 + 8) * SCST + c0 + 1] = d4[3] * 0.125f;
    }
    __syncthreads();

    for (int r = wid; r < 48; r += 4) {
        float x0 = scs[r * SCST + lane];
        float x1 = (lane < 16) ? scs[r * SCST + 32 + lane] : -1e30f;
        float mx = fmaxf(x0, x1);
        #pragma unroll
        for (int o = 16; o > 0; o >>= 1) mx = fmaxf(mx, __shfl_xor_sync(0xffffffffu, mx, o));
        float e0 = expf(x0 - mx);
        float e1 = (lane < 16) ? expf(x1 - mx) : 0.f;
        float s = e0 + e1;
        #pragma unroll
        for (int o = 16; o > 0; o >>= 1) s += __shfl_xor_sync(0xffffffffu, s, o);
        float inv = 1.f / s;
        Ph[r * PST + lane] = __float2half(e0 * inv);
        if (lane < 16) Ph[r * PST + 32 + lane] = __float2half(e1 * inv);
    }
    __syncthreads();

    for (int t = wid; t < 24; t += 4) {
        const int mf = t >> 3, nf = t & 7;
        float d4[4] = { 0.f, 0.f, 0.f, 0.f };
        #pragma unroll
        for (int ks = 0; ks < 3; ks++) {
            uint32_t a[4], b[2];
            uint32_t aaddr = pa + ((mf * 16 + (lane & 15)) * PST
                                   + ks * 16 + ((lane >> 4) << 3)) * 2;
            asm volatile("ldmatrix.sync.aligned.m8n8.x4.shared.b16 {%0,%1,%2,%3}, [%4];"
                         : "=r"(a[0]), "=r"(a[1]), "=r"(a[2]), "=r"(a[3]) : "r"(aaddr));
            uint32_t baddr = va + ((ks * 16 + (((lane >> 3) & 1) << 3) + (lane & 7)) * AST
                                   + nf * 8) * 2;
            asm volatile("ldmatrix.sync.aligned.m8n8.x2.trans.shared.b16 {%0,%1}, [%2];"
                         : "=r"(b[0]), "=r"(b[1]) : "r"(baddr));
            mma_f16(d4, a, b);
        }
        const int r0 = mf * 16 + (lane >> 2), c0 = nf * 8 + (lane & 3) * 2;
        const int g0 = order[rowbase + r0];
        const int g1 = order[rowbase + r0 + 8];
        *(uint32_t*)(out + (size_t)g0 * CC + h * DD + c0) = pack2h(d4[0], d4[1]);
        *(uint32_t*)(out + (size_t)g1 * CC + h * DD + c0) = pack2h(d4[2], d4[3]);
    }
}

// ---------------------------------------------------------------------------
// Host launch
// ---------------------------------------------------------------------------
extern "C" void kernel_launch(void* const* d_in, const int* in_sizes, int n_in,
                              void* d_out, int out_size)
{
    const float* sem_feat = (const float*)d_in[0];
    const float* bnd_feat = (const float*)d_in[1];
    const int*   order    = (const int*)d_in[2];
    const int*   inverse  = (const int*)d_in[3];
    const float* g_sem    = (const float*)d_in[4];
    const float* b_sem    = (const float*)d_in[5];
    const float* g_bnd    = (const float*)d_in[6];
    const float* b_bnd    = (const float*)d_in[7];
    const float* w_qkv_s  = (const float*)d_in[8];
    const float* b_qkv_s  = (const float*)d_in[9];
    const float* w_qkv_b  = (const float*)d_in[10];
    const float* b_qkv_b  = (const float*)d_in[11];
    const float* w_f1     = (const float*)d_in[12];
    const float* b_f1     = (const float*)d_in[13];
    const float* w_f2     = (const float*)d_in[14];
    const float* b_f2     = (const float*)d_in[15];
    const float* w_os     = (const float*)d_in[16];
    const float* b_os     = (const float*)d_in[17];
    const float* w_ob     = (const float*)d_in[18];
    const float* b_ob     = (const float*)d_in[19];
    float* out = (float*)d_out;

    __half *xln_s, *xln_b, *qkv_s, *qkv_b, *h1, *qf, *attn_s, *attn_b;
    uint32_t *wp_qs, *wp_qb, *wp_f1, *wp_f2, *wp_os, *wp_ob;
    cudaGetSymbolAddress((void**)&xln_s,  g_xln_s);
    cudaGetSymbolAddress((void**)&xln_b,  g_xln_b);
    cudaGetSymbolAddress((void**)&qkv_s,  g_qkv_s);
    cudaGetSymbolAddress((void**)&qkv_b,  g_qkv_b);
    cudaGetSymbolAddress((void**)&h1,     g_h1);
    cudaGetSymbolAddress((void**)&qf,     g_qf);
    cudaGetSymbolAddress((void**)&attn_s, g_attn_s);
    cudaGetSymbolAddress((void**)&attn_b, g_attn_b);
    cudaGetSymbolAddress((void**)&wp_qs,  g_wp_qs);
    cudaGetSymbolAddress((void**)&wp_qb,  g_wp_qb);
    cudaGetSymbolAddress((void**)&wp_f1,  g_wp_f1);
    cudaGetSymbolAddress((void**)&wp_f2,  g_wp_f2);
    cudaGetSymbolAddress((void**)&wp_os,  g_wp_os);
    cudaGetSymbolAddress((void**)&wp_ob,  g_wp_ob);

    const int SMEM_DYN = 98304;   // 3 stages x (A 16KB + B 16KB)
    cudaFuncSetAttribute(gemm_mma<0, 1>, cudaFuncAttributeMaxDynamicSharedMemorySize, SMEM_DYN);
    cudaFuncSetAttribute(gemm_mma<2, 2>, cudaFuncAttributeMaxDynamicSharedMemorySize, SMEM_DYN);
    cudaFuncSetAttribute(gemm_mma<0, 0>, cudaFuncAttributeMaxDynamicSharedMemorySize, SMEM_DYN);
    cudaFuncSetAttribute(gemm_mma<0, 3>, cudaFuncAttributeMaxDynamicSharedMemorySize, SMEM_DYN);

    // 0: pack all weights, 1: LN both streams
    prep_all<<<7168, 256>>>(w_qkv_s, w_qkv_b, w_f1, w_f2, w_os, w_ob,
                            wp_qs, wp_qb, wp_f1, wp_f2, wp_os, wp_ob);
    ln_fp16<<<dim3(NN / 8, 2), 256>>>(sem_feat, bnd_feat, g_sem, b_sem,
                                      g_bnd, b_bnd, xln_s, xln_b);

    // 2: both QKV GEMMs in one launch (grid.z picks stream)
    gemm_mma<0, 1><<<dim3(C3 / 128, NN / 128, 2), 256, SMEM_DYN>>>(
        xln_s, xln_b, nullptr, CC, wp_qs, wp_qb, C3 / 128,
        b_qkv_s, b_qkv_b, qkv_s, qkv_b, C3,
        inverse, nullptr, nullptr, CC);

    // 3: fusion MLP layer 1 (concat + GELU)
    gemm_mma<2, 2><<<dim3(C2 / 128, NN / 128), 256, SMEM_DYN>>>(
        qkv_s, qkv_s, qkv_b, C3, wp_f1, wp_f1, C2 / 128,
        b_f1, b_f1, h1, h1, C2,
        nullptr, nullptr, nullptr, C2);
    // 4: fusion MLP layer 2
    gemm_mma<0, 0><<<dim3(CC / 128, NN / 128), 256, SMEM_DYN>>>(
        h1, h1, nullptr, C2, wp_f2, wp_f2, CC / 128,
        b_f2, b_f2, qf, qf, CC,
        nullptr, nullptr, nullptr, C2);

    // 5: attention, both streams
    patch_attn_kernel<<<dim3(PP * HH, 2), 128>>>(qf, qkv_s, qkv_b, order,
                                                 attn_s, attn_b);

    // 6: both output projections + residual in one launch
    gemm_mma<0, 3><<<dim3(CC / 128, NN / 128, 2), 256, SMEM_DYN>>>(
        attn_s, attn_b, nullptr, CC, wp_os, wp_ob, CC / 128,
        b_os, b_ob, out, out + (size_t)NN * CC, CC,
        nullptr, sem_feat, bnd_feat, CC);
}